// round 1
// baseline (speedup 1.0000x reference)
#include <cuda_runtime.h>
#include <cuda_bf16.h>

#define L 2048
#define LMASK 2047
#define LSHIFT 11
// allowed class-code pairs (codes 0..3 -> bases 2,3,5,7): {0,3},{1,2},{2,3} both orders
#define PAIRMASK 0x5A48u

// ---------------- device scratch (static globals; no allocation) ----------------
__device__ float d_S[(size_t)L * L];            // masked symmetric matrix (16MB)
__device__ unsigned long long d_best[L];        // per-vertex best edge priority
__device__ int d_cls[L];                        // base class per position
__device__ int d_active[2][L];                  // ping-pong active vertex lists
__device__ int d_nActive[2];

__device__ __forceinline__ unsigned long long pack_prio(float s, int a, int b) {
    // a<b required; priority: value desc, flat index (a*L+b) asc
    unsigned k = (unsigned)(a * L + b);
    return ((unsigned long long)__float_as_uint(s) << 32) |
           (unsigned long long)(unsigned)(~k);
}

// ---------------- K1: classes + clear best ----------------
__global__ void kern_cls(const float* __restrict__ feat) {
    int i = blockIdx.x * blockDim.x + threadIdx.x;
    if (i >= L) return;
    float f0 = feat[(size_t)i * L];
    float f1 = feat[(size_t)L * L + (size_t)i * L];
    float f2 = feat[2 * (size_t)L * L + (size_t)i * L];
    float f3 = feat[3 * (size_t)L * L + (size_t)i * L];
    int c = 0; float m = f0;
    if (f1 > m) { m = f1; c = 1; }
    if (f2 > m) { m = f2; c = 2; }
    if (f3 > m) { m = f3; c = 3; }
    d_cls[i] = c;
    d_best[i] = 0ULL;
}

// ---------------- K2: build masked symmetric S + round-1 per-vertex best ----------------
__global__ void kern_build(const float* __restrict__ con) {
    int bi = blockIdx.y, bj = blockIdx.x;
    if (bj < bi) return;   // upper-triangle tiles only (uniform per block)

    __shared__ float sB[32][33];
    __shared__ float sV[32][33];
    __shared__ unsigned long long sP[32][33];
    __shared__ int clsR[32], clsC[32];

    int tx = threadIdx.x, ty = threadIdx.y;
    int i = bi * 32 + ty;
    int j = bj * 32 + tx;

    if (ty == 0) { clsR[tx] = d_cls[bi * 32 + tx]; clsC[tx] = d_cls[bj * 32 + tx]; }

    float a = con[(size_t)i * L + j];                               // tile (bi,bj), coalesced
    sB[ty][tx] = con[(size_t)(bj * 32 + ty) * L + (bi * 32 + tx)];  // tile (bj,bi), coalesced
    __syncthreads();

    float b = sB[tx][ty];          // con[j][i]
    float v = 0.5f * (a + b);
    int d = j - i;
    bool band = (d >= 4) || (d <= -4);
    bool pm = (PAIRMASK >> ((clsR[ty] << 2) | clsC[tx])) & 1u;
    float s = (band && pm) ? v : 0.0f;

    d_S[(size_t)i * L + j] = s;    // coalesced write of tile (bi,bj)
    sV[ty][tx] = s;

    unsigned long long p = 0ULL;
    if (s > 0.0f && j > i) p = pack_prio(s, i, j);
    sP[ty][tx] = p;
    __syncthreads();

    // transposed tile write (coalesced); symmetric values so diag-tile overlap is benign
    d_S[(size_t)(bj * 32 + ty) * L + (bi * 32 + tx)] = sV[tx][ty];

    // row max (vertex i): warp-reduce across tx
    unsigned long long m = p;
    #pragma unroll
    for (int o = 16; o; o >>= 1) {
        unsigned long long q = __shfl_xor_sync(0xFFFFFFFFu, m, o);
        if (q > m) m = q;
    }
    if (tx == 0 && m) atomicMax(&d_best[i], m);

    // col max (vertex j = bj*32 + ty): warp ty reduces column ty
    unsigned long long cm = sP[tx][ty];
    #pragma unroll
    for (int o = 16; o; o >>= 1) {
        unsigned long long q = __shfl_xor_sync(0xFFFFFFFFu, cm, o);
        if (q > cm) cm = q;
    }
    if (tx == 0 && cm) atomicMax(&d_best[bj * 32 + ty], cm);
}

// ---------------- per-round: recompute best over active set (multi-CTA) ----------------
__global__ void kern_best(int srcSel) {
    __shared__ int sAct[L];
    int n = d_nActive[srcSel];
    const int* act = d_active[srcSel];
    for (int t = threadIdx.x; t < n; t += blockDim.x) sAct[t] = act[t];
    __syncthreads();

    int gw = (blockIdx.x * blockDim.x + threadIdx.x) >> 5;
    int lane = threadIdx.x & 31;
    if (gw >= n) return;

    int v = sAct[gw];
    const float* __restrict__ row = d_S + (size_t)v * L;
    unsigned long long m = 0ULL;
    for (int l = lane; l < n; l += 32) {
        int u = sAct[l];
        float s = row[u];
        if (s > 0.0f) {
            unsigned long long p = (v < u) ? pack_prio(s, v, u) : pack_prio(s, u, v);
            if (p > m) m = p;
        }
    }
    #pragma unroll
    for (int o = 16; o; o >>= 1) {
        unsigned long long q = __shfl_xor_sync(0xFFFFFFFFu, m, o);
        if (q > m) m = q;
    }
    if (lane == 0) d_best[v] = m;
}

// ---------------- per-round: take mutual-best edges, write output, compact actives ----------------
// srcSel < 0 means "all 2048 vertices" (round 1). Single block of 1024 threads.
__global__ void kern_take(int srcSel, int dstSel, float* __restrict__ out) {
    __shared__ int wsum[32];
    __shared__ int sTotal;
    int t = threadIdx.x;
    int n = (srcSel < 0) ? L : d_nActive[srcSel];
    const int* act = (srcSel < 0) ? 0 : d_active[srcSel];

    int f[2]; int vv[2];
    #pragma unroll
    for (int r = 0; r < 2; r++) {
        int idx = 2 * t + r;
        int fl = 0, v = -1;
        if (idx < n) {
            v = act ? act[idx] : idx;
            unsigned long long b = d_best[v];
            if (b) {
                unsigned k = ~((unsigned)b);
                int i = (int)(k >> LSHIFT), j = (int)(k & LMASK);
                int u = (v == i) ? j : i;
                if (d_best[u] == b) {
                    if (v == i) {   // write once per pair
                        float val = __uint_as_float((unsigned)(b >> 32));
                        out[i * L + j] = val;
                        out[j * L + i] = val;
                    }
                } else fl = 1;      // survives
            }
        }
        f[r] = fl; vv[r] = v;
    }

    // block exclusive scan over per-thread sums
    int sum = f[0] + f[1];
    int lane = t & 31, wid = t >> 5;
    int x = sum;
    #pragma unroll
    for (int o = 1; o < 32; o <<= 1) { int y = __shfl_up_sync(0xFFFFFFFFu, x, o); if (lane >= o) x += y; }
    if (lane == 31) wsum[wid] = x;
    __syncthreads();
    if (wid == 0) {
        int z = wsum[lane];
        #pragma unroll
        for (int o = 1; o < 32; o <<= 1) { int y = __shfl_up_sync(0xFFFFFFFFu, z, o); if (lane >= o) z += y; }
        wsum[lane] = z;
        if (lane == 31) sTotal = z;
    }
    __syncthreads();
    int ex = (wid ? wsum[wid - 1] : 0) + x - sum;
    int* dst = d_active[dstSel];
    if (f[0]) dst[ex] = vv[0];
    if (f[1]) dst[ex + f[0]] = vv[1];
    if (t == 0) d_nActive[dstSel] = sTotal;
}

// ---------------- persistent single-block kernel: all remaining rounds ----------------
__global__ void kern_finish(int srcSel, float* __restrict__ out) {
    __shared__ int sAct[L];
    __shared__ int sTmp[L];
    __shared__ unsigned long long sBest[L];
    __shared__ int wsum[32];
    __shared__ int sTotal;

    int t = threadIdx.x;              // 1024 threads
    int lane = t & 31, wid = t >> 5;
    int n = d_nActive[srcSel];
    for (int x = t; x < n; x += 1024) sAct[x] = d_active[srcSel][x];
    __syncthreads();

    while (n > 0) {
        // phase A: per-active-vertex best (warp per vertex, strided)
        for (int a = wid; a < n; a += 32) {
            int v = sAct[a];
            const float* __restrict__ row = d_S + (size_t)v * L;
            unsigned long long m = 0ULL;
            for (int l = lane; l < n; l += 32) {
                int u = sAct[l];
                float s = row[u];
                if (s > 0.0f) {
                    unsigned long long p = (v < u) ? pack_prio(s, v, u) : pack_prio(s, u, v);
                    if (p > m) m = p;
                }
            }
            #pragma unroll
            for (int o = 16; o; o >>= 1) {
                unsigned long long q = __shfl_xor_sync(0xFFFFFFFFu, m, o);
                if (q > m) m = q;
            }
            if (lane == 0) sBest[v] = m;
        }
        __syncthreads();

        // phase B: take + compact
        int f[2]; int vv[2];
        #pragma unroll
        for (int r = 0; r < 2; r++) {
            int idx = 2 * t + r;
            int fl = 0, v = -1;
            if (idx < n) {
                v = sAct[idx];
                unsigned long long b = sBest[v];
                if (b) {
                    unsigned k = ~((unsigned)b);
                    int i = (int)(k >> LSHIFT), j = (int)(k & LMASK);
                    int u = (v == i) ? j : i;
                    if (sBest[u] == b) {
                        if (v == i) {
                            float val = __uint_as_float((unsigned)(b >> 32));
                            out[i * L + j] = val;
                            out[j * L + i] = val;
                        }
                    } else fl = 1;
                }
            }
            f[r] = fl; vv[r] = v;
        }
        int sum = f[0] + f[1];
        int x = sum;
        #pragma unroll
        for (int o = 1; o < 32; o <<= 1) { int y = __shfl_up_sync(0xFFFFFFFFu, x, o); if (lane >= o) x += y; }
        if (lane == 31) wsum[wid] = x;
        __syncthreads();
        if (wid == 0) {
            int z = wsum[lane];
            #pragma unroll
            for (int o = 1; o < 32; o <<= 1) { int y = __shfl_up_sync(0xFFFFFFFFu, z, o); if (lane >= o) z += y; }
            wsum[lane] = z;
            if (lane == 31) sTotal = z;
        }
        __syncthreads();
        int ex = (wid ? wsum[wid - 1] : 0) + x - sum;
        if (f[0]) sTmp[ex] = vv[0];
        if (f[1]) sTmp[ex + f[0]] = vv[1];
        __syncthreads();
        int nn = sTotal;
        for (int x2 = t; x2 < nn; x2 += 1024) sAct[x2] = sTmp[x2];
        n = nn;
        __syncthreads();
    }
}

// ---------------- launch ----------------
extern "C" void kernel_launch(void* const* d_in, const int* in_sizes, int n_in,
                              void* d_out, int out_size) {
    const float* con  = (const float*)d_in[0];
    const float* feat = (const float*)d_in[1];
    if (n_in >= 2 && in_sizes[0] > in_sizes[1]) {   // feat (8L^2) is the bigger one
        const float* tmp = con; con = feat; feat = tmp;
    }
    float* out = (float*)d_out;

    cudaMemsetAsync(out, 0, (size_t)L * L * sizeof(float));

    kern_cls<<<(L + 1023) / 1024, 1024>>>(feat);

    dim3 gb(L / 32, L / 32), tb(32, 32);
    kern_build<<<gb, tb>>>(con);                 // round-1 best fused here

    kern_take<<<1, 1024>>>(-1, 0, out);          // round 1 take -> active[0]

    kern_best<<<64, 1024>>>(0);                  // round 2
    kern_take<<<1, 1024>>>(0, 1, out);

    kern_best<<<64, 1024>>>(1);                  // round 3
    kern_take<<<1, 1024>>>(1, 0, out);

    kern_best<<<64, 1024>>>(0);                  // round 4
    kern_take<<<1, 1024>>>(0, 1, out);

    kern_finish<<<1, 1024>>>(1, out);            // all remaining rounds
}